// round 1
// baseline (speedup 1.0000x reference)
#include <cuda_runtime.h>
#include <math.h>

#define B_   16
#define L_   512
#define HID_ 768
#define HEADS_ 12
#define M_   4
#define EMB_ 768
#define BLK_ 8
#define NER_ 6
#define NCLS_ 97
#define XDIM_ (2*HID_ + NER_)   // 1542
#define XPAD_ 1544

// ---------------- scratch (no allocation allowed) ----------------
__device__ float g_hs [B_*HID_];
__device__ float g_ts [B_*HID_];
__device__ float g_ht [B_*L_];
__device__ float g_rs [B_*HID_];
__device__ float g_hs2[B_*EMB_];
__device__ float g_ts2[B_*EMB_];

// ---------------- K1: gather + logsumexp + ht_att (grid = B) ----------------
__global__ void k1_gather(const float* __restrict__ seq,
                          const float* __restrict__ attn,
                          const int*   __restrict__ epos)
{
    const int b   = blockIdx.x;
    const int tid = threadIdx.x;

    __shared__ int s_start[8];
    if (tid < 8) s_start[tid] = epos[b*8 + tid] + 1;
    __syncthreads();

    int s0[M_], s1[M_];
#pragma unroll
    for (int m = 0; m < M_; m++) { s0[m] = s_start[m]; s1[m] = s_start[4+m]; }

    // --- entity embeddings: logsumexp over the 4 mentions; also zero rs ---
    const float* seqb = seq + (size_t)b * L_ * HID_;
    for (int d = tid; d < HID_; d += blockDim.x) {
        float v0[M_], v1[M_];
#pragma unroll
        for (int m = 0; m < M_; m++) {
            v0[m] = seqb[(size_t)s0[m]*HID_ + d];
            v1[m] = seqb[(size_t)s1[m]*HID_ + d];
        }
        float mx0 = fmaxf(fmaxf(v0[0], v0[1]), fmaxf(v0[2], v0[3]));
        float mx1 = fmaxf(fmaxf(v1[0], v1[1]), fmaxf(v1[2], v1[3]));
        float e0 = expf(v0[0]-mx0) + expf(v0[1]-mx0) + expf(v0[2]-mx0) + expf(v0[3]-mx0);
        float e1 = expf(v1[0]-mx1) + expf(v1[1]-mx1) + expf(v1[2]-mx1) + expf(v1[3]-mx1);
        g_hs[b*HID_ + d] = mx0 + logf(e0);
        g_ts[b*HID_ + d] = mx1 + logf(e1);
        g_rs[b*HID_ + d] = 0.0f;   // zeroed for K2's atomics
    }

    // --- ht_att ---
    __shared__ float sht[L_];
    __shared__ float sred[256];
    const float* ab = attn + (size_t)b * HEADS_ * L_ * L_;
    float lsum = 0.0f;
    for (int l = tid; l < L_; l += blockDim.x) {
        float acc = 0.0f;
#pragma unroll 1
        for (int h = 0; h < HEADS_; h++) {
            const float* ah = ab + (size_t)h * L_ * L_;
            float a0 = 0.0f, a1 = 0.0f;
#pragma unroll
            for (int m = 0; m < M_; m++) {
                a0 += ah[(size_t)s0[m]*L_ + l];
                a1 += ah[(size_t)s1[m]*L_ + l];
            }
            acc += a0 * a1;
        }
        acc *= (1.0f / (4.0f * 4.0f * (float)HEADS_));
        sht[l] = acc;
        lsum += acc;
    }
    sred[tid] = lsum;
    __syncthreads();
    for (int s = 128; s > 0; s >>= 1) {
        if (tid < s) sred[tid] += sred[tid + s];
        __syncthreads();
    }
    const float inv = 1.0f / (sred[0] + 1e-5f);
    for (int l = tid; l < L_; l += blockDim.x)
        g_ht[b*L_ + l] = sht[l] * inv;
}

// ---------------- K2: rs = sum_l seq[b,l,:] * ht[b,l] (grid = 8 x B) ----------------
__global__ void k2_rs(const float* __restrict__ seq)
{
    const int b     = blockIdx.y;
    const int chunk = blockIdx.x;       // 8 chunks of 64 l each
    const int tid   = threadIdx.x;      // 256 threads, 3 dims each
    const int l0    = chunk * 64;

    const float* seqb = seq + ((size_t)b * L_ + l0) * HID_;
    const float* htb  = g_ht + b*L_ + l0;

    float a0 = 0.f, a1 = 0.f, a2 = 0.f;
#pragma unroll 4
    for (int l = 0; l < 64; l++) {
        const float w = htb[l];
        const float* row = seqb + (size_t)l * HID_;
        a0 = fmaf(row[tid      ], w, a0);
        a1 = fmaf(row[tid + 256], w, a1);
        a2 = fmaf(row[tid + 512], w, a2);
    }
    atomicAdd(&g_rs[b*HID_ + tid      ], a0);
    atomicAdd(&g_rs[b*HID_ + tid + 256], a1);
    atomicAdd(&g_rs[b*HID_ + tid + 512], a2);
}

// ---------------- K3: hs2/ts2 = tanh([e, rs, ner] @ W.T + b) (grid = 96) ----------------
// blocks 0..47 -> Wh/hs, blocks 48..95 -> Wt/ts. Each block: 16 output rows,
// 8 warps x 2 rows, all 16 batches per warp. x lives in dynamic smem.
__global__ void __launch_bounds__(256, 1) k3_gemm(
    const float* __restrict__ Wh, const float* __restrict__ bh,
    const float* __restrict__ Wt, const float* __restrict__ bt,
    const float* __restrict__ hs_ner, const float* __restrict__ ts_ner)
{
    extern __shared__ float xsh[];  // B_ * XPAD_
    const int half  = blockIdx.x / 48;
    const int obase = (blockIdx.x % 48) * 16;
    const int tid   = threadIdx.x;

    const float* Wsel = half ? Wt : Wh;
    const float* bias = half ? bt : bh;
    const float* emb  = half ? g_ts : g_hs;
    const float* ner  = half ? ts_ner : hs_ner;
    float*       outb = half ? g_ts2 : g_hs2;

    for (int idx = tid; idx < B_*XDIM_; idx += blockDim.x) {
        const int b = idx / XDIM_;
        const int k = idx - b*XDIM_;
        float v;
        if (k < HID_)            v = emb[b*HID_ + k];
        else if (k < 2*HID_)     v = g_rs[b*HID_ + (k - HID_)];
        else                     v = ner[b*NER_ + (k - 2*HID_)];
        xsh[b*XPAD_ + k] = v;
    }
    __syncthreads();

    const int w    = tid >> 5;
    const int lane = tid & 31;
    const int o0   = obase + w*2;
    const int o1   = o0 + 1;

    float acc0[B_], acc1[B_];
#pragma unroll
    for (int b = 0; b < B_; b++) { acc0[b] = 0.f; acc1[b] = 0.f; }

    const float* W0 = Wsel + (size_t)o0 * XDIM_;
    const float* W1 = Wsel + (size_t)o1 * XDIM_;

    for (int k = lane; k < XDIM_; k += 32) {
        const float w0 = W0[k];
        const float w1 = W1[k];
#pragma unroll
        for (int b = 0; b < B_; b++) {
            const float xv = xsh[b*XPAD_ + k];
            acc0[b] = fmaf(w0, xv, acc0[b]);
            acc1[b] = fmaf(w1, xv, acc1[b]);
        }
    }

#pragma unroll
    for (int b = 0; b < B_; b++) {
#pragma unroll
        for (int off = 16; off > 0; off >>= 1) {
            acc0[b] += __shfl_down_sync(0xffffffffu, acc0[b], off);
            acc1[b] += __shfl_down_sync(0xffffffffu, acc1[b], off);
        }
    }
    if (lane == 0) {
        const float bi0 = bias[o0], bi1 = bias[o1];
#pragma unroll
        for (int b = 0; b < B_; b++) {
            outb[b*EMB_ + o0] = tanhf(acc0[b] + bi0);
            outb[b*EMB_ + o1] = tanhf(acc1[b] + bi1);
        }
    }
}

// ---------------- K4: bilinear block-product + logits (grid = NCLS) ----------------
__global__ void __launch_bounds__(256, 1) k4_logits(
    const float* __restrict__ Wb, const float* __restrict__ bb,
    float* __restrict__ out)
{
    extern __shared__ float sm[];
    float* hsh = sm;                  // B_*EMB_
    float* tsh = sm + B_*EMB_;        // B_*EMB_
    float* red = tsh + B_*EMB_;       // 8*B_

    const int c   = blockIdx.x;
    const int tid = threadIdx.x;

    for (int i = tid; i < B_*EMB_; i += blockDim.x) {
        hsh[i] = g_hs2[i];
        tsh[i] = g_ts2[i];
    }
    __syncthreads();

    float acc[B_];
#pragma unroll
    for (int b = 0; b < B_; b++) acc[b] = 0.f;

    const float* Wc = Wb + (size_t)c * (EMB_*BLK_);
    for (int j = tid; j < EMB_*BLK_; j += blockDim.x) {
        const float wv  = Wc[j];
        const int hidx  = j >> 3;                        // g*8 + i
        const int tidx  = ((j >> 6) << 3) | (j & 7);     // g*8 + k
#pragma unroll
        for (int b = 0; b < B_; b++)
            acc[b] = fmaf(wv, hsh[b*EMB_ + hidx] * tsh[b*EMB_ + tidx], acc[b]);
    }

    const int w = tid >> 5, lane = tid & 31;
#pragma unroll
    for (int b = 0; b < B_; b++) {
#pragma unroll
        for (int off = 16; off > 0; off >>= 1)
            acc[b] += __shfl_down_sync(0xffffffffu, acc[b], off);
    }
    if (lane == 0) {
#pragma unroll
        for (int b = 0; b < B_; b++) red[w*B_ + b] = acc[b];
    }
    __syncthreads();
    if (tid < B_) {
        float s = bb[c];
#pragma unroll
        for (int w2 = 0; w2 < 8; w2++) s += red[w2*B_ + tid];
        out[tid*NCLS_ + c] = s;
    }
}

// ---------------- launch ----------------
extern "C" void kernel_launch(void* const* d_in, const int* in_sizes, int n_in,
                              void* d_out, int out_size)
{
    const float* seq    = (const float*)d_in[0];
    const float* attn   = (const float*)d_in[1];
    const int*   epos   = (const int*)  d_in[2];
    const float* hs_ner = (const float*)d_in[3];
    const float* ts_ner = (const float*)d_in[4];
    const float* Wh     = (const float*)d_in[5];
    const float* bh     = (const float*)d_in[6];
    const float* Wt     = (const float*)d_in[7];
    const float* bt     = (const float*)d_in[8];
    const float* Wb     = (const float*)d_in[9];
    const float* bb     = (const float*)d_in[10];
    float* out = (float*)d_out;

    const int smem_k3 = B_ * XPAD_ * 4;                    // 98816 B
    const int smem_k4 = (2*B_*EMB_ + 8*B_) * 4;            // 98816 B
    cudaFuncSetAttribute(k3_gemm,   cudaFuncAttributeMaxDynamicSharedMemorySize, smem_k3);
    cudaFuncSetAttribute(k4_logits, cudaFuncAttributeMaxDynamicSharedMemorySize, smem_k4);

    k1_gather<<<B_, 256>>>(seq, attn, epos);
    dim3 g2(8, B_);
    k2_rs<<<g2, 256>>>(seq);
    k3_gemm<<<96, 256, smem_k3>>>(Wh, bh, Wt, bt, hs_ner, ts_ner);
    k4_logits<<<NCLS_, 256, smem_k4>>>(Wb, bb, out);
}